// round 1
// baseline (speedup 1.0000x reference)
#include <cuda_runtime.h>

// Problem constants: N = 262144, C = 128.
//   d_in[0] vector_embeddings [N,128,3] f32
//   d_in[1] scalar_embeddings [N,128]   f32
//   d_in[2] U_w [128,128]  (out,in)
//   d_in[3] V_w [128,128]
//   d_in[4] W1  [128,256]
//   d_in[5] b1  [128]
//   d_in[6] W2  [384,128]
//   d_in[7] b2  [384]
// d_out: delta_v [N,128,3] followed by delta_s [N,128]  (N*512 floats)

#define TILE_M 32

// Transposed-weight scratch (device globals: allocation-free scratch per harness rules)
__device__ float g_Ut[128 * 128];   // Ut[c][o] = U_w[o][c]
__device__ float g_Vt[128 * 128];   // Vt[c][o] = V_w[o][c]
__device__ float g_W1t[256 * 128];  // W1t[k][o] = W1[o][k]
__device__ float g_W2t[128 * 384];  // W2t[h][j] = W2[j][h]

__global__ void prep_kernel(const float* __restrict__ U_w, const float* __restrict__ V_w,
                            const float* __restrict__ W1, const float* __restrict__ W2) {
    int t = blockIdx.x * blockDim.x + threadIdx.x;
    if (t < 16384) {
        int c = t >> 7, o = t & 127;
        g_Ut[t] = U_w[o * 128 + c];
        g_Vt[t] = V_w[o * 128 + c];
    }
    if (t < 32768) {
        int k = t >> 7, o = t & 127;
        g_W1t[t] = W1[o * 256 + k];
    }
    if (t < 49152) {
        int h = t / 384, j = t - h * 384;
        g_W2t[t] = W2[j * 128 + h];
    }
}

__global__ __launch_bounds__(256, 1)
void update_kernel(const float* __restrict__ ve, const float* __restrict__ se,
                   const float* __restrict__ b1, const float* __restrict__ b2,
                   float* __restrict__ out, int N) {
    extern __shared__ float sm[];
    float* sA = sm;           // 12288 f: phase1 = ve tile [32][384]; phase2 = mvec[32][256] + h[32][128] @ +8192
    float* sU = sm + 12288;   // 12288 f: u tile, layout [m][i*128+o]
    float* sW = sm + 24576;   // 12288 f: weight chunk staging / delta_v output staging

    const int t  = threadIdx.x;
    const int tm = t >> 4;        // 0..15
    const int to = t & 15;        // 0..15
    const int m0 = tm << 1;       // owns rows m0, m0+1
    const int o0 = to << 3;       // owns cols o0..o0+7
    const long long n0 = (long long)blockIdx.x * TILE_M;

    // ---- load ve tile (contiguous 48KB, coalesced float4) ----
    {
        const float4* src = (const float4*)(ve + n0 * 384);
        float4* dst = (float4*)sA;
        #pragma unroll
        for (int q = 0; q < 12; q++) dst[t + q * 256] = src[t + q * 256];
    }
    __syncthreads();

    float dotp[2][8], vn2[2][8];
    #pragma unroll
    for (int r = 0; r < 2; r++)
        #pragma unroll
        for (int j = 0; j < 8; j++) { dotp[r][j] = 0.f; vn2[r][j] = 0.f; }

    // ================= u/v GEMMs: per spatial component i =================
    #pragma unroll 1
    for (int i = 0; i < 3; i++) {
        float au[2][8], av[2][8];
        #pragma unroll
        for (int r = 0; r < 2; r++)
            #pragma unroll
            for (int j = 0; j < 8; j++) { au[r][j] = 0.f; av[r][j] = 0.f; }

        #pragma unroll 1
        for (int kc = 0; kc < 4; kc++) {             // K chunks of 32
            __syncthreads();                         // previous sW readers done
            {
                const float4* su = (const float4*)(g_Ut + kc * 4096);
                const float4* sv = (const float4*)(g_Vt + kc * 4096);
                float4* du = (float4*)sW;
                float4* dv = (float4*)(sW + 4096);
                #pragma unroll
                for (int q = 0; q < 4; q++) {
                    du[t + q * 256] = su[t + q * 256];
                    dv[t + q * 256] = sv[t + q * 256];
                }
            }
            __syncthreads();
            const float* xr0 = sA + m0 * 384 + kc * 96 + i;  // x[m][c] = sA[m*384 + c*3 + i]
            const float* xr1 = xr0 + 384;
            #pragma unroll 4
            for (int cl = 0; cl < 32; cl++) {
                float x0 = xr0[cl * 3];
                float x1 = xr1[cl * 3];
                float uu[8], vv[8];
                *(float4*)(uu)     = *(const float4*)(sW + cl * 128 + o0);
                *(float4*)(uu + 4) = *(const float4*)(sW + cl * 128 + o0 + 4);
                *(float4*)(vv)     = *(const float4*)(sW + 4096 + cl * 128 + o0);
                *(float4*)(vv + 4) = *(const float4*)(sW + 4096 + cl * 128 + o0 + 4);
                #pragma unroll
                for (int j = 0; j < 8; j++) {
                    au[0][j] += x0 * uu[j];
                    au[1][j] += x1 * uu[j];
                    av[0][j] += x0 * vv[j];
                    av[1][j] += x1 * vv[j];
                }
            }
        }
        // stash u, accumulate dot & |v|^2
        #pragma unroll
        for (int r = 0; r < 2; r++)
            #pragma unroll
            for (int j = 0; j < 8; j++) {
                float uv = au[r][j], vv_ = av[r][j];
                sU[(m0 + r) * 384 + i * 128 + o0 + j] = uv;
                dotp[r][j] += uv * vv_;
                vn2[r][j]  += vv_ * vv_;
            }
    }

    // ================= build mvec = [scalar | vnorm] =================
    __syncthreads();   // ve tile (sA) dead; all sW readers done
    {
        const float4* src = (const float4*)(se + n0 * 128);
        #pragma unroll
        for (int q = 0; q < 4; q++) {
            int idx = t + q * 256;        // 0..1023 float4s
            int m   = idx >> 5;           // 32 float4 per row
            int k4  = idx & 31;
            *(float4*)(sA + m * 256 + (k4 << 2)) = src[idx];
        }
    }
    #pragma unroll
    for (int r = 0; r < 2; r++)
        #pragma unroll
        for (int j = 0; j < 8; j++)
            sA[(m0 + r) * 256 + 128 + o0 + j] = sqrtf(vn2[r][j] + 1e-8f);
    __syncthreads();

    // ================= MLP layer 1: [32,256] @ W1t -> silu -> h [32,128] =================
    float hh[2][8];
    #pragma unroll
    for (int r = 0; r < 2; r++)
        #pragma unroll
        for (int j = 0; j < 8; j++) hh[r][j] = 0.f;

    #pragma unroll 1
    for (int kc = 0; kc < 8; kc++) {
        {
            const float4* src = (const float4*)(g_W1t + kc * 4096);
            float4* dst = (float4*)sW;
            #pragma unroll
            for (int q = 0; q < 4; q++) dst[t + q * 256] = src[t + q * 256];
        }
        __syncthreads();
        const float* xr0 = sA + m0 * 256 + kc * 32;
        const float* xr1 = xr0 + 256;
        #pragma unroll 4
        for (int kl = 0; kl < 32; kl++) {
            float x0 = xr0[kl], x1 = xr1[kl];
            float w[8];
            *(float4*)(w)     = *(const float4*)(sW + kl * 128 + o0);
            *(float4*)(w + 4) = *(const float4*)(sW + kl * 128 + o0 + 4);
            #pragma unroll
            for (int j = 0; j < 8; j++) {
                hh[0][j] += x0 * w[j];
                hh[1][j] += x1 * w[j];
            }
        }
        __syncthreads();
    }
    {
        float bb[8];
        *(float4*)(bb)     = __ldg((const float4*)(b1 + o0));
        *(float4*)(bb + 4) = __ldg((const float4*)(b1 + o0 + 4));
        #pragma unroll
        for (int r = 0; r < 2; r++)
            #pragma unroll
            for (int j = 0; j < 8; j++) {
                float z = hh[r][j] + bb[j];
                float s = __fdividef(z, 1.f + __expf(-z));   // silu
                sA[8192 + (m0 + r) * 128 + o0 + j] = s;
            }
    }

    // ================= MLP layer 2: h [32,128] @ W2t -> a,b,c [32,128] each =================
    float aA[2][8], aB[2][8], aC[2][8];
    #pragma unroll
    for (int r = 0; r < 2; r++)
        #pragma unroll
        for (int j = 0; j < 8; j++) { aA[r][j] = 0.f; aB[r][j] = 0.f; aC[r][j] = 0.f; }

    #pragma unroll 1
    for (int kc = 0; kc < 4; kc++) {
        {
            const float4* src = (const float4*)(g_W2t + kc * 32 * 384);
            float4* dst = (float4*)sW;
            #pragma unroll
            for (int q = 0; q < 12; q++) dst[t + q * 256] = src[t + q * 256];
        }
        __syncthreads();   // also publishes h (sA+8192) on kc==0
        const float* xr0 = sA + 8192 + m0 * 128 + kc * 32;
        const float* xr1 = xr0 + 128;
        #pragma unroll 2
        for (int hl = 0; hl < 32; hl++) {
            float x0 = xr0[hl], x1 = xr1[hl];
            const float* w = sW + hl * 384;
            float wa[8], wb[8], wc[8];
            *(float4*)(wa)     = *(const float4*)(w + o0);
            *(float4*)(wa + 4) = *(const float4*)(w + o0 + 4);
            *(float4*)(wb)     = *(const float4*)(w + 128 + o0);
            *(float4*)(wb + 4) = *(const float4*)(w + 128 + o0 + 4);
            *(float4*)(wc)     = *(const float4*)(w + 256 + o0);
            *(float4*)(wc + 4) = *(const float4*)(w + 256 + o0 + 4);
            #pragma unroll
            for (int j = 0; j < 8; j++) {
                aA[0][j] += x0 * wa[j];  aA[1][j] += x1 * wa[j];
                aB[0][j] += x0 * wb[j];  aB[1][j] += x1 * wb[j];
                aC[0][j] += x0 * wc[j];  aC[1][j] += x1 * wc[j];
            }
        }
        __syncthreads();
    }

    // ================= epilogue =================
    float ba[8], bb_[8], bc[8];
    *(float4*)(ba)      = __ldg((const float4*)(b2 + o0));
    *(float4*)(ba + 4)  = __ldg((const float4*)(b2 + o0 + 4));
    *(float4*)(bb_)     = __ldg((const float4*)(b2 + 128 + o0));
    *(float4*)(bb_ + 4) = __ldg((const float4*)(b2 + 128 + o0 + 4));
    *(float4*)(bc)      = __ldg((const float4*)(b2 + 256 + o0));
    *(float4*)(bc + 4)  = __ldg((const float4*)(b2 + 256 + o0 + 4));

    float* ds_base = out + (long long)N * 384;
    #pragma unroll
    for (int r = 0; r < 2; r++) {
        float dsv[8];
        #pragma unroll
        for (int j = 0; j < 8; j++) {
            float bv = aB[r][j] + bb_[j];
            float cv = aC[r][j] + bc[j];
            dsv[j] = bv + cv * dotp[r][j];
        }
        float4* dst = (float4*)(ds_base + (n0 + m0 + r) * 128 + o0);
        dst[0] = *(float4*)(dsv);
        dst[1] = *(float4*)(dsv + 4);

        // delta_v staged in sW (reused) for coalesced store
        #pragma unroll
        for (int j = 0; j < 8; j++) {
            float av_ = aA[r][j] + ba[j];
            int ob = (m0 + r) * 384 + (o0 + j) * 3;
            int ub = (m0 + r) * 384 + o0 + j;
            sW[ob + 0] = av_ * sU[ub];
            sW[ob + 1] = av_ * sU[ub + 128];
            sW[ob + 2] = av_ * sU[ub + 256];
        }
    }
    __syncthreads();
    {
        const float4* src = (const float4*)sW;
        float4* dst = (float4*)(out + n0 * 384);
        #pragma unroll
        for (int q = 0; q < 12; q++) dst[t + q * 256] = src[t + q * 256];
    }
}

extern "C" void kernel_launch(void* const* d_in, const int* in_sizes, int n_in,
                              void* d_out, int out_size) {
    const float* ve = (const float*)d_in[0];
    const float* se = (const float*)d_in[1];
    const float* Uw = (const float*)d_in[2];
    const float* Vw = (const float*)d_in[3];
    const float* W1 = (const float*)d_in[4];
    const float* b1 = (const float*)d_in[5];
    const float* W2 = (const float*)d_in[6];
    const float* b2 = (const float*)d_in[7];
    float* out = (float*)d_out;

    const int N = in_sizes[0] / 384;        // 262144
    const int smem_bytes = 36864 * 4;       // 144 KB

    cudaFuncSetAttribute(update_kernel, cudaFuncAttributeMaxDynamicSharedMemorySize, smem_bytes);

    prep_kernel<<<192, 256>>>(Uw, Vw, W1, W2);
    update_kernel<<<N / TILE_M, 256, smem_bytes>>>(ve, se, b1, b2, out, N);
}

// round 2
// speedup vs baseline: 2.4692x; 2.4692x over previous
#include <cuda_runtime.h>

// Problem: N = 262144, C = 128.
//   d_in: ve [N,128,3], se [N,128], U_w[128,128], V_w[128,128],
//         W1[128,256], b1[128], W2[384,128], b2[384]
//   d_out: delta_v [N,128,3] then delta_s [N,128]

typedef unsigned long long u64;

#define FMA2(d,a,b)  asm("fma.rn.f32x2 %0, %1, %2, %0;" : "+l"(d) : "l"(a), "l"(b))
#define DUP2(d,x)    asm("mov.b64 %0, {%1, %1};" : "=l"(d) : "r"(__float_as_uint(x)))
#define LDS2U64(a,b,addr) asm volatile("ld.shared.v2.u64 {%0, %1}, [%2];" : "=l"(a), "=l"(b) : "r"(addr))
#define UNPACK2(lo,hi,v) { unsigned _l,_h; asm("mov.b64 {%0, %1}, %2;" : "=r"(_l), "=r"(_h) : "l"(v)); lo=__uint_as_float(_l); hi=__uint_as_float(_h); }

// Transposed-weight scratch (device globals = allowed scratch)
__device__ float g_Ut[128 * 128];   // Ut[c][o]
__device__ float g_Vt[128 * 128];
__device__ float g_W1t[256 * 128];  // W1t[k][o]
__device__ float g_W2t[128 * 384];  // W2t[h][j]

__global__ void prep_kernel(const float* __restrict__ U_w, const float* __restrict__ V_w,
                            const float* __restrict__ W1, const float* __restrict__ W2) {
    int t = blockIdx.x * blockDim.x + threadIdx.x;
    if (t < 16384) {
        int c = t >> 7, o = t & 127;
        g_Ut[t] = U_w[o * 128 + c];
        g_Vt[t] = V_w[o * 128 + c];
    }
    if (t < 32768) {
        int k = t >> 7, o = t & 127;
        g_W1t[t] = W1[o * 256 + k];
    }
    if (t < 49152) {
        int h = t / 384, j = t - h * 384;
        g_W2t[t] = W2[j * 128 + h];
    }
}

// smem: sA 12288 f (ve tile -> mvec[32][256]+h[32][128]) | sW 4096 f staging | sDot 4096 f
__global__ __launch_bounds__(256, 2)
void update_kernel(const float* __restrict__ ve, const float* __restrict__ se,
                   const float* __restrict__ b1, const float* __restrict__ b2,
                   float* __restrict__ out, int N) {
    extern __shared__ float sm[];
    float* sA   = sm;
    float* sW   = sm + 12288;
    float* sDot = sm + 16384;
    const unsigned smb = (unsigned)__cvta_generic_to_shared(sm);
    const unsigned sWb = smb + 12288 * 4;

    const int t  = threadIdx.x;
    const int tm = t >> 5;          // warp id 0..7  -> rows
    const int to = t & 31;          // lane          -> cols
    const int m0 = tm << 2;         // 4 rows
    const int o0 = to << 2;         // 4 cols
    const long long n0 = (long long)blockIdx.x * 32;

    // ---- load ve tile [32][384] coalesced ----
    {
        const float4* src = (const float4*)(ve + n0 * 384);
        float4* dst = (float4*)sA;
        #pragma unroll
        for (int q = 0; q < 12; q++) dst[t + q * 256] = src[t + q * 256];
    }

    u64 uacc[3][4][2];     // persistent u tile (packed col pairs)
    u64 vn2p[4][2];
    #pragma unroll
    for (int m = 0; m < 4; m++) { vn2p[m][0] = 0ULL; vn2p[m][1] = 0ULL; }

    // ================= u/v GEMMs =================
    #pragma unroll
    for (int i = 0; i < 3; i++) {
        u64 va[4][2];
        #pragma unroll
        for (int m = 0; m < 4; m++) {
            uacc[i][m][0] = 0ULL; uacc[i][m][1] = 0ULL;
            va[m][0] = 0ULL; va[m][1] = 0ULL;
        }
        #pragma unroll 1
        for (int kc = 0; kc < 8; kc++) {          // 16-k chunks
            __syncthreads();
            {
                const float4* su = (const float4*)(g_Ut + kc * 2048);
                const float4* sv = (const float4*)(g_Vt + kc * 2048);
                float4* du = (float4*)sW;
                float4* dv = (float4*)(sW + 2048);
                du[t] = su[t]; du[t + 256] = su[t + 256];
                dv[t] = sv[t]; dv[t + 256] = sv[t + 256];
            }
            __syncthreads();
            const float* xp = sA + m0 * 384 + kc * 48 + i;   // x[m][k] stride-3
            const unsigned wu_base = sWb + o0 * 4;
            const unsigned wv_base = wu_base + 8192;
            #pragma unroll 8
            for (int kl = 0; kl < 16; kl++) {
                float x0 = xp[kl * 3];
                float x1 = xp[kl * 3 + 384];
                float x2 = xp[kl * 3 + 768];
                float x3 = xp[kl * 3 + 1152];
                u64 xd0, xd1, xd2, xd3;
                DUP2(xd0, x0); DUP2(xd1, x1); DUP2(xd2, x2); DUP2(xd3, x3);
                u64 wu0, wu1, wv0, wv1;
                LDS2U64(wu0, wu1, wu_base + kl * 512);
                LDS2U64(wv0, wv1, wv_base + kl * 512);
                FMA2(uacc[i][0][0], xd0, wu0); FMA2(uacc[i][0][1], xd0, wu1);
                FMA2(uacc[i][1][0], xd1, wu0); FMA2(uacc[i][1][1], xd1, wu1);
                FMA2(uacc[i][2][0], xd2, wu0); FMA2(uacc[i][2][1], xd2, wu1);
                FMA2(uacc[i][3][0], xd3, wu0); FMA2(uacc[i][3][1], xd3, wu1);
                FMA2(va[0][0], xd0, wv0); FMA2(va[0][1], xd0, wv1);
                FMA2(va[1][0], xd1, wv0); FMA2(va[1][1], xd1, wv1);
                FMA2(va[2][0], xd2, wv0); FMA2(va[2][1], xd2, wv1);
                FMA2(va[3][0], xd3, wv0); FMA2(va[3][1], xd3, wv1);
            }
        }
        // vn2 += v*v (regs), dot += u*v (smem RMW, exclusive cells)
        #pragma unroll
        for (int m = 0; m < 4; m++) {
            FMA2(vn2p[m][0], va[m][0], va[m][0]);
            FMA2(vn2p[m][1], va[m][1], va[m][1]);
            u64* dp = (u64*)(sDot + (m0 + m) * 128 + o0);
            u64 d0 = (i == 0) ? 0ULL : dp[0];
            u64 d1 = (i == 0) ? 0ULL : dp[1];
            FMA2(d0, uacc[i][m][0], va[m][0]);
            FMA2(d1, uacc[i][m][1], va[m][1]);
            dp[0] = d0; dp[1] = d1;
        }
    }

    // ================= mvec = [scalar | vnorm] into sA =================
    __syncthreads();   // ve tile dead
    {
        const float4* src = (const float4*)(se + n0 * 128);
        #pragma unroll
        for (int q = 0; q < 4; q++) {
            int idx = t + q * 256;
            int m = idx >> 5, k4 = idx & 31;
            ((float4*)sA)[m * 64 + k4] = src[idx];
        }
    }
    #pragma unroll
    for (int m = 0; m < 4; m++) {
        float lo, hi;
        UNPACK2(lo, hi, vn2p[m][0]);
        sA[(m0 + m) * 256 + 128 + o0 + 0] = sqrtf(lo + 1e-8f);
        sA[(m0 + m) * 256 + 128 + o0 + 1] = sqrtf(hi + 1e-8f);
        UNPACK2(lo, hi, vn2p[m][1]);
        sA[(m0 + m) * 256 + 128 + o0 + 2] = sqrtf(lo + 1e-8f);
        sA[(m0 + m) * 256 + 128 + o0 + 3] = sqrtf(hi + 1e-8f);
    }

    // ================= MLP1: [32,256]@W1t -> silu -> h =================
    u64 hh[4][2];
    #pragma unroll
    for (int m = 0; m < 4; m++) { hh[m][0] = 0ULL; hh[m][1] = 0ULL; }
    #pragma unroll 1
    for (int kc = 0; kc < 16; kc++) {
        __syncthreads();
        {
            const float4* src = (const float4*)(g_W1t + kc * 2048);
            float4* d = (float4*)sW;
            d[t] = src[t]; d[t + 256] = src[t + 256];
        }
        __syncthreads();
        const float* xp = sA + m0 * 256 + kc * 16;
        const unsigned w_base = sWb + o0 * 4;
        #pragma unroll 8
        for (int kl = 0; kl < 16; kl++) {
            float x0 = xp[kl], x1 = xp[kl + 256], x2 = xp[kl + 512], x3 = xp[kl + 768];
            u64 xd0, xd1, xd2, xd3;
            DUP2(xd0, x0); DUP2(xd1, x1); DUP2(xd2, x2); DUP2(xd3, x3);
            u64 w0, w1;
            LDS2U64(w0, w1, w_base + kl * 512);
            FMA2(hh[0][0], xd0, w0); FMA2(hh[0][1], xd0, w1);
            FMA2(hh[1][0], xd1, w0); FMA2(hh[1][1], xd1, w1);
            FMA2(hh[2][0], xd2, w0); FMA2(hh[2][1], xd2, w1);
            FMA2(hh[3][0], xd3, w0); FMA2(hh[3][1], xd3, w1);
        }
    }
    {
        float4 bb = __ldg((const float4*)(b1 + o0));
        float bbv[4] = {bb.x, bb.y, bb.z, bb.w};
        #pragma unroll
        for (int m = 0; m < 4; m++) {
            float z[4];
            UNPACK2(z[0], z[1], hh[m][0]);
            UNPACK2(z[2], z[3], hh[m][1]);
            #pragma unroll
            for (int j = 0; j < 4; j++) {
                float v = z[j] + bbv[j];
                sA[8192 + (m0 + m) * 128 + o0 + j] = __fdividef(v, 1.f + __expf(-v));
            }
        }
    }

    // ================= MLP2: h[32,128]@W2t -> a,b,c =================
    u64 aA[4][2], aB[4][2], aC[4][2];
    #pragma unroll
    for (int m = 0; m < 4; m++) {
        aA[m][0]=0ULL; aA[m][1]=0ULL; aB[m][0]=0ULL; aB[m][1]=0ULL; aC[m][0]=0ULL; aC[m][1]=0ULL;
    }
    #pragma unroll 1
    for (int kc = 0; kc < 16; kc++) {         // 8-k chunks
        __syncthreads();
        {
            const float4* src = (const float4*)(g_W2t + kc * 3072);
            float4* d = (float4*)sW;
            d[t] = src[t]; d[t + 256] = src[t + 256]; d[t + 512] = src[t + 512];
        }
        __syncthreads();
        const float* xp = sA + 8192 + m0 * 128 + kc * 8;
        const unsigned w_base = sWb + o0 * 4;
        #pragma unroll
        for (int kl = 0; kl < 8; kl++) {
            float x0 = xp[kl], x1 = xp[kl + 128], x2 = xp[kl + 256], x3 = xp[kl + 384];
            u64 xd0, xd1, xd2, xd3;
            DUP2(xd0, x0); DUP2(xd1, x1); DUP2(xd2, x2); DUP2(xd3, x3);
            u64 wa0, wa1, wb0, wb1, wc0, wc1;
            LDS2U64(wa0, wa1, w_base + kl * 1536);
            LDS2U64(wb0, wb1, w_base + kl * 1536 + 512);
            LDS2U64(wc0, wc1, w_base + kl * 1536 + 1024);
            FMA2(aA[0][0], xd0, wa0); FMA2(aA[0][1], xd0, wa1);
            FMA2(aA[1][0], xd1, wa0); FMA2(aA[1][1], xd1, wa1);
            FMA2(aA[2][0], xd2, wa0); FMA2(aA[2][1], xd2, wa1);
            FMA2(aA[3][0], xd3, wa0); FMA2(aA[3][1], xd3, wa1);
            FMA2(aB[0][0], xd0, wb0); FMA2(aB[0][1], xd0, wb1);
            FMA2(aB[1][0], xd1, wb0); FMA2(aB[1][1], xd1, wb1);
            FMA2(aB[2][0], xd2, wb0); FMA2(aB[2][1], xd2, wb1);
            FMA2(aB[3][0], xd3, wb0); FMA2(aB[3][1], xd3, wb1);
            FMA2(aC[0][0], xd0, wc0); FMA2(aC[0][1], xd0, wc1);
            FMA2(aC[1][0], xd1, wc0); FMA2(aC[1][1], xd1, wc1);
            FMA2(aC[2][0], xd2, wc0); FMA2(aC[2][1], xd2, wc1);
            FMA2(aC[3][0], xd3, wc0); FMA2(aC[3][1], xd3, wc1);
        }
    }

    // ================= epilogue =================
    float4 b2a = __ldg((const float4*)(b2 + o0));
    float4 b2b = __ldg((const float4*)(b2 + 128 + o0));
    float4 b2c = __ldg((const float4*)(b2 + 256 + o0));
    float bav[4] = {b2a.x, b2a.y, b2a.z, b2a.w};
    float bbv2[4] = {b2b.x, b2b.y, b2b.z, b2b.w};
    float bcv[4] = {b2c.x, b2c.y, b2c.z, b2c.w};

    float* ds_base = out + (long long)N * 384;
    #pragma unroll
    for (int m = 0; m < 4; m++) {
        float Bv[4], Cv[4], Dv[4];
        UNPACK2(Bv[0], Bv[1], aB[m][0]); UNPACK2(Bv[2], Bv[3], aB[m][1]);
        UNPACK2(Cv[0], Cv[1], aC[m][0]); UNPACK2(Cv[2], Cv[3], aC[m][1]);
        const float* dpf = sDot + (m0 + m) * 128 + o0;
        Dv[0] = dpf[0]; Dv[1] = dpf[1]; Dv[2] = dpf[2]; Dv[3] = dpf[3];
        float4 dsv;
        dsv.x = (Bv[0] + bbv2[0]) + (Cv[0] + bcv[0]) * Dv[0];
        dsv.y = (Bv[1] + bbv2[1]) + (Cv[1] + bcv[1]) * Dv[1];
        dsv.z = (Bv[2] + bbv2[2]) + (Cv[2] + bcv[2]) * Dv[2];
        dsv.w = (Bv[3] + bbv2[3]) + (Cv[3] + bcv[3]) * Dv[3];
        *(float4*)(ds_base + (n0 + m0 + m) * 128 + o0) = dsv;
    }

    __syncthreads();   // all MLP2/h reads done; reuse sA as delta_v staging
    #pragma unroll
    for (int m = 0; m < 4; m++) {
        float Av[4];
        UNPACK2(Av[0], Av[1], aA[m][0]); UNPACK2(Av[2], Av[3], aA[m][1]);
        float uu[3][4];
        #pragma unroll
        for (int i = 0; i < 3; i++) {
            UNPACK2(uu[i][0], uu[i][1], uacc[i][m][0]);
            UNPACK2(uu[i][2], uu[i][3], uacc[i][m][1]);
        }
        #pragma unroll
        for (int j = 0; j < 4; j++) {
            float a = Av[j] + bav[j];
            int base = (m0 + m) * 384 + (o0 + j) * 3;
            sA[base + 0] = a * uu[0][j];
            sA[base + 1] = a * uu[1][j];
            sA[base + 2] = a * uu[2][j];
        }
    }
    __syncthreads();
    {
        const float4* src = (const float4*)sA;
        float4* dst = (float4*)(out + n0 * 384);
        #pragma unroll
        for (int q = 0; q < 12; q++) dst[t + q * 256] = src[t + q * 256];
    }
}

extern "C" void kernel_launch(void* const* d_in, const int* in_sizes, int n_in,
                              void* d_out, int out_size) {
    const float* ve = (const float*)d_in[0];
    const float* se = (const float*)d_in[1];
    const float* Uw = (const float*)d_in[2];
    const float* Vw = (const float*)d_in[3];
    const float* W1 = (const float*)d_in[4];
    const float* b1 = (const float*)d_in[5];
    const float* W2 = (const float*)d_in[6];
    const float* b2 = (const float*)d_in[7];
    float* out = (float*)d_out;

    const int N = in_sizes[0] / 384;         // 262144
    const int smem_bytes = 20480 * 4;        // 80 KB -> 2 CTAs/SM

    cudaFuncSetAttribute(update_kernel, cudaFuncAttributeMaxDynamicSharedMemorySize, smem_bytes);

    prep_kernel<<<192, 256>>>(Uw, Vw, W1, W2);
    update_kernel<<<N / 32, 256, smem_bytes>>>(ve, se, b1, b2, out, N);
}

// round 4
// speedup vs baseline: 3.8374x; 1.5541x over previous
#include <cuda_runtime.h>
#include <cuda_bf16.h>

typedef unsigned int u32;
typedef unsigned short u16;
typedef unsigned long long u64;

// Problem: N=262144 tokens, C=128.
//   d_in: ve [N,128,3] f32, se [N,128], U_w[128,128], V_w[128,128],
//         W1[128,256], b1[128], W2[384,128], b2[384]
//   out: delta_v [N,128,3] then delta_s [N,128]
//
// All GEMMs via mma.sync m16n8k16 bf16 with hi/lo 3-term split.
// Weight images pre-swizzled in device globals: [256 rows (hi 0-127 | lo 128-255)][128 cols]
// images: 0=U^T, 1=V^T, 2=W1^T k-half0, 3=W1^T k-half1, 4..6=W2^T n-tiles a,b,c

__device__ __align__(16) u16 g_img[7][32768];

__host__ __device__ __forceinline__ int img_byte(int r, int c) {
    return r * 256 + ((((c >> 3) ^ (r & 7)) << 4) | ((c & 7) << 1));
}

__global__ void prep_kernel(const float* __restrict__ U, const float* __restrict__ V,
                            const float* __restrict__ W1, const float* __restrict__ W2) {
    int t = blockIdx.x * blockDim.x + threadIdx.x;
    if (t >= 7 * 32768) return;
    int img = t >> 15, e = t & 32767;
    int r = e >> 7, n = e & 127, k = r & 127;
    float val;
    switch (img) {
        case 0:  val = U[n * 128 + k]; break;
        case 1:  val = V[n * 128 + k]; break;
        case 2:  val = W1[n * 256 + k]; break;
        case 3:  val = W1[n * 256 + 128 + k]; break;
        case 4:  val = W2[n * 128 + k]; break;
        case 5:  val = W2[(128 + n) * 128 + k]; break;
        default: val = W2[(256 + n) * 128 + k]; break;
    }
    __nv_bfloat16 h = __float2bfloat16(val);
    u16 w = (r < 128) ? __bfloat16_as_ushort(h)
                      : __bfloat16_as_ushort(__float2bfloat16(val - __bfloat162float(h)));
    g_img[img][img_byte(r, n) >> 1] = w;
}

// ---------------- device helpers ----------------
__device__ __forceinline__ u32 a_addr(u32 Ab, int r, int c) {   // A tile: 64 rows x 1KB, swizzled
    return Ab + r * 1024 + ((((c >> 3) ^ (r & 7)) << 4) | ((c & 7) << 1));
}
__device__ __forceinline__ void split2(float x0, float x1, u32& hi, u32& lo) {
    __nv_bfloat16 h0 = __float2bfloat16(x0), h1 = __float2bfloat16(x1);
    __nv_bfloat16 l0 = __float2bfloat16(x0 - __bfloat162float(h0));
    __nv_bfloat16 l1 = __float2bfloat16(x1 - __bfloat162float(h1));
    hi = ((u32)__bfloat16_as_ushort(h1) << 16) | __bfloat16_as_ushort(h0);
    lo = ((u32)__bfloat16_as_ushort(l1) << 16) | __bfloat16_as_ushort(l0);
}
#define STS32(a, v)      asm volatile("st.shared.u32 [%0], %1;" :: "r"(a), "r"(v))
#define LDS2F(x, y, a)   asm volatile("ld.shared.v2.f32 {%0,%1}, [%2];" : "=f"(x), "=f"(y) : "r"(a))
#define STS2F(a, x, y)   asm volatile("st.shared.v2.f32 [%0], {%1,%2};" :: "r"(a), "f"(x), "f"(y))
#define CP_COMMIT        asm volatile("cp.async.commit_group;")
#define CP_WAIT0         asm volatile("cp.async.wait_group 0;" ::: "memory")

__device__ __forceinline__ void cp_img(u32 sdst, const u16* src, int t) {
    #pragma unroll
    for (int q = 0; q < 8; q++) {
        int idx = t + q * 512;
        asm volatile("cp.async.cg.shared.global [%0], [%1], 16;"
                     :: "r"(sdst + idx * 16), "l"((const char*)src + idx * 16));
    }
}

// one split-term: C[m16,n32] += A[m16, aoff..aoff+128) * B[boff..boff+128, n32)
__device__ __forceinline__ void gemm_term(float* acc, u32 Ab, u32 Bb,
                                          int mb, int nb, int lane, int aoff, int boff) {
    const int ra = mb + (lane & 15);
    const int half8 = (lane >> 4) << 3;
    const int rbl = lane & 15;
    #pragma unroll
    for (int kc = 0; kc < 8; kc++) {
        int col = aoff + kc * 16 + half8;
        u32 aaddr = Ab + ra * 1024 + ((((col >> 3) ^ (ra & 7)) << 4));
        u32 a0, a1, a2, a3;
        asm volatile("ldmatrix.sync.aligned.m8n8.x4.shared.b16 {%0,%1,%2,%3}, [%4];"
                     : "=r"(a0), "=r"(a1), "=r"(a2), "=r"(a3) : "r"(aaddr));
        int rb = boff + kc * 16 + rbl;
        u32 brow = Bb + rb * 256;
        #pragma unroll
        for (int np = 0; np < 2; np++) {
            int cb = nb + np * 16 + half8;
            u32 baddr = brow + ((((cb >> 3) ^ (rb & 7)) << 4));
            u32 b0, b1, b2, b3;
            asm volatile("ldmatrix.sync.aligned.m8n8.x4.trans.shared.b16 {%0,%1,%2,%3}, [%4];"
                         : "=r"(b0), "=r"(b1), "=r"(b2), "=r"(b3) : "r"(baddr));
            float* d0 = acc + np * 8;
            float* d1 = acc + np * 8 + 4;
            asm volatile("mma.sync.aligned.m16n8k16.row.col.f32.bf16.bf16.f32 "
                         "{%0,%1,%2,%3},{%4,%5,%6,%7},{%8,%9},{%0,%1,%2,%3};"
                         : "+f"(d0[0]), "+f"(d0[1]), "+f"(d0[2]), "+f"(d0[3])
                         : "r"(a0), "r"(a1), "r"(a2), "r"(a3), "r"(b0), "r"(b1));
            asm volatile("mma.sync.aligned.m16n8k16.row.col.f32.bf16.bf16.f32 "
                         "{%0,%1,%2,%3},{%4,%5,%6,%7},{%8,%9},{%0,%1,%2,%3};"
                         : "+f"(d1[0]), "+f"(d1[1]), "+f"(d1[2]), "+f"(d1[3])
                         : "r"(a0), "r"(a1), "r"(a2), "r"(a3), "r"(b2), "r"(b3));
        }
    }
}
// 3-term split GEMM: hi*Bh + lo*Bh + hi*Bl
__device__ __forceinline__ void gemm3(float* acc, u32 Ab, u32 Bb,
                                      int mb, int nb, int lane, int ah, int al) {
    gemm_term(acc, Ab, Bb, mb, nb, lane, ah, 0);
    gemm_term(acc, Ab, Bb, mb, nb, lane, al, 0);
    gemm_term(acc, Ab, Bb, mb, nb, lane, ah, 128);
}

__device__ __forceinline__ void fill_x(u32 Ab, const float* __restrict__ ve,
                                       long long n0, int i, int t) {
    #pragma unroll
    for (int q = 0; q < 8; q++) {
        int p = t + q * 512;
        int r = p >> 6, c0 = (p & 63) << 1;
        const float* g = ve + (n0 + r) * 384 + c0 * 3 + i;
        float x0 = __ldg(g), x1 = __ldg(g + 3);
        u32 hi, lo;
        split2(x0, x1, hi, lo);
        STS32(a_addr(Ab, r, c0), hi);
        STS32(a_addr(Ab, r, 128 + c0), lo);
    }
}

// ---------------- main kernel ----------------
// smem: A tile 64KB (rows 64 x 1KB; cols 0-511 operand, bytes 512-1023/row = vn2 scratch
//       during phase A), B0 @64KB, B1 @128KB
__global__ __launch_bounds__(512, 1)
void update_kernel(const float* __restrict__ ve, const float* __restrict__ se,
                   const float* __restrict__ b1, const float* __restrict__ b2,
                   float* __restrict__ out, int Ntok) {
    extern __shared__ __align__(128) unsigned char smraw[];
    const u32 Ab = (u32)__cvta_generic_to_shared(smraw);
    const u32 B0 = Ab + 65536, B1 = Ab + 131072;

    const int t = threadIdx.x, lane = t & 31, warp = t >> 5;
    const int mb = (warp >> 2) << 4;      // 0,16,32,48
    const int nb = (warp & 3) << 5;       // 0,32,64,96
    const int g8 = lane >> 2, tid2 = (lane & 3) << 1;
    const long long n0 = (long long)blockIdx.x * 64;

    cp_img(B0, g_img[0], t);              // U
    cp_img(B1, g_img[1], t);              // V
    CP_COMMIT;
    fill_x(Ab, ve, n0, 0, t);
    CP_WAIT0;
    __syncthreads();

    float dot[16], uacc[3][16];
    #pragma unroll
    for (int x = 0; x < 16; x++) dot[x] = 0.f;

    // ======== phase A: u_i, v_i, dot, vn2 ========
    #pragma unroll
    for (int i = 0; i < 3; i++) {
        float vacc[16];
        #pragma unroll
        for (int x = 0; x < 16; x++) { uacc[i][x] = 0.f; vacc[x] = 0.f; }
        gemm3(uacc[i], Ab, B0, mb, nb, lane, 0, 128);
        gemm3(vacc,    Ab, B1, mb, nb, lane, 0, 128);
        #pragma unroll
        for (int x = 0; x < 16; x++) dot[x] = fmaf(uacc[i][x], vacc[x], dot[x]);
        #pragma unroll
        for (int nt = 0; nt < 4; nt++)
            #pragma unroll
            for (int jr = 0; jr < 2; jr++) {
                int r = mb + g8 + jr * 8;
                int c0 = nb + nt * 8 + tid2;
                u32 ad = Ab + r * 1024 + 512 + c0 * 4;
                float v0 = vacc[nt * 4 + jr * 2], v1 = vacc[nt * 4 + jr * 2 + 1];
                if (i == 0) {
                    STS2F(ad, v0 * v0, v1 * v1);
                } else {
                    float p0, p1;
                    LDS2F(p0, p1, ad);
                    STS2F(ad, fmaf(v0, v0, p0), fmaf(v1, v1, p1));
                }
            }
        if (i < 2) {
            __syncthreads();
            fill_x(Ab, ve, n0, i + 1, t);
            __syncthreads();
        }
    }

    // ======== mvec = [se | vnorm] ========
    float vnr[16];
    #pragma unroll
    for (int nt = 0; nt < 4; nt++)
        #pragma unroll
        for (int jr = 0; jr < 2; jr++) {
            int r = mb + g8 + jr * 8;
            int c0 = nb + nt * 8 + tid2;
            LDS2F(vnr[nt * 4 + jr * 2], vnr[nt * 4 + jr * 2 + 1], Ab + r * 1024 + 512 + c0 * 4);
        }
    __syncthreads();
    cp_img(B0, g_img[2], t);              // W1 k-half0
    cp_img(B1, g_img[3], t);              // W1 k-half1
    CP_COMMIT;
    #pragma unroll
    for (int q = 0; q < 8; q++) {         // se -> cols 0-255
        int p = t + q * 512;
        int r = p >> 6, c0 = (p & 63) << 1;
        float2 v = *(const float2*)(se + (n0 + r) * 128 + c0);
        u32 hi, lo;
        split2(v.x, v.y, hi, lo);
        STS32(a_addr(Ab, r, c0), hi);
        STS32(a_addr(Ab, r, 128 + c0), lo);
    }
    #pragma unroll
    for (int nt = 0; nt < 4; nt++)        // vnorm -> cols 256-511
        #pragma unroll
        for (int jr = 0; jr < 2; jr++) {
            int r = mb + g8 + jr * 8;
            int c0 = nb + nt * 8 + tid2;
            float s0 = sqrtf(vnr[nt * 4 + jr * 2] + 1e-8f);
            float s1 = sqrtf(vnr[nt * 4 + jr * 2 + 1] + 1e-8f);
            u32 hi, lo;
            split2(s0, s1, hi, lo);
            STS32(a_addr(Ab, r, 256 + c0), hi);
            STS32(a_addr(Ab, r, 384 + c0), lo);
        }
    CP_WAIT0;
    __syncthreads();

    // ======== MLP1 ========
    float hacc[16];
    #pragma unroll
    for (int x = 0; x < 16; x++) hacc[x] = 0.f;
    gemm3(hacc, Ab, B0, mb, nb, lane, 0, 128);
    gemm3(hacc, Ab, B1, mb, nb, lane, 256, 384);
    __syncthreads();
    cp_img(B0, g_img[4], t);              // W2 tile a
    cp_img(B1, g_img[5], t);              // W2 tile b
    CP_COMMIT;
    #pragma unroll
    for (int nt = 0; nt < 4; nt++)        // silu(h) -> A cols 0-255
        #pragma unroll
        for (int jr = 0; jr < 2; jr++) {
            int r = mb + g8 + jr * 8;
            int c0 = nb + nt * 8 + tid2;
            float z0 = hacc[nt * 4 + jr * 2]     + __ldg(b1 + c0);
            float z1 = hacc[nt * 4 + jr * 2 + 1] + __ldg(b1 + c0 + 1);
            float s0 = __fdividef(z0, 1.f + __expf(-z0));
            float s1 = __fdividef(z1, 1.f + __expf(-z1));
            u32 hi, lo;
            split2(s0, s1, hi, lo);
            STS32(a_addr(Ab, r, c0), hi);
            STS32(a_addr(Ab, r, 128 + c0), lo);
        }
    CP_WAIT0;
    __syncthreads();

    // ======== MLP2 tile a + delta_v ========
    float aacc[16];
    #pragma unroll
    for (int x = 0; x < 16; x++) aacc[x] = 0.f;
    gemm3(aacc, Ab, B0, mb, nb, lane, 0, 128);
    __syncthreads();                      // B0 free
    cp_img(B0, g_img[6], t);              // W2 tile c (overlaps epilogue + b-tile mma)
    CP_COMMIT;
    #pragma unroll
    for (int nt = 0; nt < 4; nt++)
        #pragma unroll
        for (int jr = 0; jr < 2; jr++) {
            int r = mb + g8 + jr * 8;
            #pragma unroll
            for (int jc = 0; jc < 2; jc++) {
                int c = nb + nt * 8 + tid2 + jc;
                int idx = nt * 4 + jr * 2 + jc;
                float a = aacc[idx] + __ldg(b2 + c);
                float* dst = out + (n0 + r) * 384 + c * 3;
                dst[0] = a * uacc[0][idx];
                dst[1] = a * uacc[1][idx];
                dst[2] = a * uacc[2][idx];
            }
        }

    float bacc[16];
    #pragma unroll
    for (int x = 0; x < 16; x++) bacc[x] = 0.f;
    gemm3(bacc, Ab, B1, mb, nb, lane, 0, 128);
    CP_WAIT0;
    __syncthreads();

    float cacc[16];
    #pragma unroll
    for (int x = 0; x < 16; x++) cacc[x] = 0.f;
    gemm3(cacc, Ab, B0, mb, nb, lane, 0, 128);

    float* ds = out + (long long)Ntok * 384;
    #pragma unroll
    for (int nt = 0; nt < 4; nt++)
        #pragma unroll
        for (int jr = 0; jr < 2; jr++) {
            int r = mb + g8 + jr * 8;
            int c0 = nb + nt * 8 + tid2;
            int idx = nt * 4 + jr * 2;
            float d0 = (bacc[idx]     + __ldg(b2 + 128 + c0))
                     + (cacc[idx]     + __ldg(b2 + 256 + c0))     * dot[idx];
            float d1 = (bacc[idx + 1] + __ldg(b2 + 129 + c0))
                     + (cacc[idx + 1] + __ldg(b2 + 257 + c0))     * dot[idx + 1];
            *(float2*)(ds + (n0 + r) * 128 + c0) = make_float2(d0, d1);
        }
}

extern "C" void kernel_launch(void* const* d_in, const int* in_sizes, int n_in,
                              void* d_out, int out_size) {
    const float* ve = (const float*)d_in[0];
    const float* se = (const float*)d_in[1];
    const float* Uw = (const float*)d_in[2];
    const float* Vw = (const float*)d_in[3];
    const float* W1 = (const float*)d_in[4];
    const float* b1 = (const float*)d_in[5];
    const float* W2 = (const float*)d_in[6];
    const float* b2 = (const float*)d_in[7];
    float* out = (float*)d_out;

    const int N = in_sizes[0] / 384;        // 262144
    const int smem_bytes = 196608;          // 192 KB

    cudaFuncSetAttribute(update_kernel, cudaFuncAttributeMaxDynamicSharedMemorySize, smem_bytes);

    prep_kernel<<<448, 512>>>(Uw, Vw, W1, W2);
    update_kernel<<<N / 64, 512, smem_bytes>>>(ve, se, b1, b2, out, N);
}

// round 5
// speedup vs baseline: 4.0245x; 1.0487x over previous
#include <cuda_runtime.h>
#include <cuda_bf16.h>

typedef unsigned int u32;
typedef unsigned short u16;

// Problem: N=262144 tokens, C=128.
//   d_in: ve [N,128,3] f32, se [N,128], U_w[128,128], V_w[128,128],
//         W1[128,256], b1[128], W2[384,128], b2[384]
//   out: delta_v [N,128,3] then delta_s [N,128]
//
// mma.sync m16n8k16 bf16, hi/lo 3-term split. CTA = 64 tokens, 512 threads,
// split into 2 independent 8-warp groups (32 tokens each) with private A/B smem
// and named barriers, so one group's MMAs hide the other's loads/epilogues.
// Weight images (pre-swizzled, [256 rows hi|lo][128 cols]) in device globals:
// 0=U^T 1=V^T 2=W1^T k0 3=W1^T k1 4..6=W2^T a,b,c

__device__ __align__(16) u16 g_img[7][32768];

__host__ __device__ __forceinline__ int img_byte(int r, int c) {
    return r * 256 + ((((c >> 3) ^ (r & 7)) << 4) | ((c & 7) << 1));
}

__global__ void prep_kernel(const float* __restrict__ U, const float* __restrict__ V,
                            const float* __restrict__ W1, const float* __restrict__ W2) {
    int t = blockIdx.x * blockDim.x + threadIdx.x;
    if (t >= 7 * 32768) return;
    int img = t >> 15, e = t & 32767;
    int r = e >> 7, n = e & 127, k = r & 127;
    float val;
    switch (img) {
        case 0:  val = U[n * 128 + k]; break;
        case 1:  val = V[n * 128 + k]; break;
        case 2:  val = W1[n * 256 + k]; break;
        case 3:  val = W1[n * 256 + 128 + k]; break;
        case 4:  val = W2[n * 128 + k]; break;
        case 5:  val = W2[(128 + n) * 128 + k]; break;
        default: val = W2[(256 + n) * 128 + k]; break;
    }
    __nv_bfloat16 h = __float2bfloat16(val);
    u16 w = (r < 128) ? __bfloat16_as_ushort(h)
                      : __bfloat16_as_ushort(__float2bfloat16(val - __bfloat162float(h)));
    g_img[img][img_byte(r, n) >> 1] = w;
}

// ---------------- device helpers ----------------
__device__ __forceinline__ u32 a_addr(u32 Ab, int r, int c) {   // A tile: 32 rows x 1KB
    return Ab + r * 1024 + ((((c >> 3) ^ (r & 7)) << 4) | ((c & 7) << 1));
}
__device__ __forceinline__ void split2(float x0, float x1, u32& hi, u32& lo) {
    __nv_bfloat16 h0 = __float2bfloat16(x0), h1 = __float2bfloat16(x1);
    __nv_bfloat16 l0 = __float2bfloat16(x0 - __bfloat162float(h0));
    __nv_bfloat16 l1 = __float2bfloat16(x1 - __bfloat162float(h1));
    hi = ((u32)__bfloat16_as_ushort(h1) << 16) | __bfloat16_as_ushort(h0);
    lo = ((u32)__bfloat16_as_ushort(l1) << 16) | __bfloat16_as_ushort(l0);
}
#define STS32(a, v)  asm volatile("st.shared.u32 [%0], %1;" :: "r"(a), "r"(v))
#define CP_COMMIT    asm volatile("cp.async.commit_group;")
#define CP_WAIT0     asm volatile("cp.async.wait_group 0;" ::: "memory")
#define BARG         asm volatile("bar.sync %0, 256;" :: "r"(gid + 1) : "memory")

__device__ __forceinline__ void cp_img(u32 sdst, const u16* src, int tg) {
    #pragma unroll
    for (int q = 0; q < 16; q++) {
        int idx = tg + q * 256;
        asm volatile("cp.async.cg.shared.global [%0], [%1], 16;"
                     :: "r"(sdst + idx * 16), "l"((const char*)src + idx * 16));
    }
}

// C[m16,n32] += A[m16, aoff..+128) * B[boff..+128, n32)
__device__ __forceinline__ void gemm_term(float* acc, u32 Ab, u32 Bb,
                                          int mb, int nb, int lane, int aoff, int boff) {
    const int ra = mb + (lane & 15);
    const int half8 = (lane >> 4) << 3;
    const int rbl = lane & 15;
    #pragma unroll
    for (int kc = 0; kc < 8; kc++) {
        int col = aoff + kc * 16 + half8;
        u32 aaddr = Ab + ra * 1024 + ((((col >> 3) ^ (ra & 7)) << 4));
        u32 a0, a1, a2, a3;
        asm volatile("ldmatrix.sync.aligned.m8n8.x4.shared.b16 {%0,%1,%2,%3}, [%4];"
                     : "=r"(a0), "=r"(a1), "=r"(a2), "=r"(a3) : "r"(aaddr));
        int rb = boff + kc * 16 + rbl;
        u32 brow = Bb + rb * 256;
        #pragma unroll
        for (int np = 0; np < 2; np++) {
            int cb = nb + np * 16 + half8;
            u32 baddr = brow + ((((cb >> 3) ^ (rb & 7)) << 4));
            u32 b0, b1, b2, b3;
            asm volatile("ldmatrix.sync.aligned.m8n8.x4.trans.shared.b16 {%0,%1,%2,%3}, [%4];"
                         : "=r"(b0), "=r"(b1), "=r"(b2), "=r"(b3) : "r"(baddr));
            float* d0 = acc + np * 8;
            float* d1 = acc + np * 8 + 4;
            asm volatile("mma.sync.aligned.m16n8k16.row.col.f32.bf16.bf16.f32 "
                         "{%0,%1,%2,%3},{%4,%5,%6,%7},{%8,%9},{%0,%1,%2,%3};"
                         : "+f"(d0[0]), "+f"(d0[1]), "+f"(d0[2]), "+f"(d0[3])
                         : "r"(a0), "r"(a1), "r"(a2), "r"(a3), "r"(b0), "r"(b1));
            asm volatile("mma.sync.aligned.m16n8k16.row.col.f32.bf16.bf16.f32 "
                         "{%0,%1,%2,%3},{%4,%5,%6,%7},{%8,%9},{%0,%1,%2,%3};"
                         : "+f"(d1[0]), "+f"(d1[1]), "+f"(d1[2]), "+f"(d1[3])
                         : "r"(a0), "r"(a1), "r"(a2), "r"(a3), "r"(b2), "r"(b3));
        }
    }
}
__device__ __forceinline__ void gemm3(float* acc, u32 Ab, u32 Bb,
                                      int mb, int nb, int lane, int ah, int al) {
    gemm_term(acc, Ab, Bb, mb, nb, lane, ah, 0);
    gemm_term(acc, Ab, Bb, mb, nb, lane, al, 0);
    gemm_term(acc, Ab, Bb, mb, nb, lane, ah, 128);
}

// fill x_i (component i of ve) -> A cols 0-127 hi, 128-255 lo (group: 32 rows)
__device__ __forceinline__ void fill_x(u32 Ab, const float* __restrict__ ve,
                                       long long g0, int i, int tg) {
    #pragma unroll
    for (int q = 0; q < 8; q++) {
        int p = tg + q * 256;
        int r = p >> 6, c0 = (p & 63) << 1;
        const float* g = ve + (g0 + r) * 384 + c0 * 3 + i;
        float x0 = __ldg(g), x1 = __ldg(g + 3);
        u32 hi, lo;
        split2(x0, x1, hi, lo);
        STS32(a_addr(Ab, r, c0), hi);
        STS32(a_addr(Ab, r, 128 + c0), lo);
    }
}

// ---------------- main kernel ----------------
// smem: A0 @0 (32KB), A1 @32KB, B0 @64KB (64KB), B1 @128KB   -> 192KB
__global__ __launch_bounds__(512, 1)
void update_kernel(const float* __restrict__ ve, const float* __restrict__ se,
                   const float* __restrict__ b1, const float* __restrict__ b2,
                   float* __restrict__ out, int Ntok) {
    extern __shared__ __align__(128) unsigned char smraw[];
    const u32 smb = (u32)__cvta_generic_to_shared(smraw);

    const int t = threadIdx.x, lane = t & 31;
    const int gid = t >> 8;                 // group 0 / 1
    const int tg = t & 255;                 // thread-in-group
    const int wg = (t >> 5) & 7;            // warp-in-group
    const int mb = (wg >> 2) << 4;          // 0,16
    const int nb = (wg & 3) << 5;           // 0,32,64,96
    const int g8 = lane >> 2, tid2 = (lane & 3) << 1;
    const long long g0 = (long long)blockIdx.x * 64 + gid * 32;   // first token of group

    const u32 Ab = smb + gid * 32768;
    const u32 Bb = smb + 65536 + gid * 65536;

    // ======== phase A: u_i (B=U), then v_i (B=V) ========
    cp_img(Bb, g_img[0], tg);
    CP_COMMIT;
    fill_x(Ab, ve, g0, 0, tg);
    CP_WAIT0;
    BARG;

    float uacc[3][16], dot[16], vn2[16];
    #pragma unroll
    for (int x = 0; x < 16; x++) { dot[x] = 0.f; vn2[x] = 0.f; }

    #pragma unroll
    for (int i = 0; i < 3; i++) {
        #pragma unroll
        for (int x = 0; x < 16; x++) uacc[i][x] = 0.f;
        gemm3(uacc[i], Ab, Bb, mb, nb, lane, 0, 128);
        if (i < 2) { BARG; fill_x(Ab, ve, g0, i + 1, tg); BARG; }
    }
    BARG;
    cp_img(Bb, g_img[1], tg);               // V
    CP_COMMIT;
    fill_x(Ab, ve, g0, 0, tg);
    CP_WAIT0;
    BARG;
    #pragma unroll
    for (int i = 0; i < 3; i++) {
        float vacc[16];
        #pragma unroll
        for (int x = 0; x < 16; x++) vacc[x] = 0.f;
        gemm3(vacc, Ab, Bb, mb, nb, lane, 0, 128);
        #pragma unroll
        for (int x = 0; x < 16; x++) {
            dot[x] = fmaf(uacc[i][x], vacc[x], dot[x]);
            vn2[x] = fmaf(vacc[x], vacc[x], vn2[x]);
        }
        if (i < 2) { BARG; fill_x(Ab, ve, g0, i + 1, tg); BARG; }
    }

    // ======== MLP1: h = silu([se|vnorm] @ W1^T + b1), two K-passes ========
    BARG;
    cp_img(Bb, g_img[2], tg);               // W1 k-half0
    CP_COMMIT;
    #pragma unroll
    for (int q = 0; q < 8; q++) {           // se -> A cols 0-255
        int p = tg + q * 256;
        int r = p >> 6, c0 = (p & 63) << 1;
        float2 v = *(const float2*)(se + (g0 + r) * 128 + c0);
        u32 hi, lo;
        split2(v.x, v.y, hi, lo);
        STS32(a_addr(Ab, r, c0), hi);
        STS32(a_addr(Ab, r, 128 + c0), lo);
    }
    CP_WAIT0;
    BARG;
    float hacc[16];
    #pragma unroll
    for (int x = 0; x < 16; x++) hacc[x] = 0.f;
    gemm3(hacc, Ab, Bb, mb, nb, lane, 0, 128);

    BARG;
    cp_img(Bb, g_img[3], tg);               // W1 k-half1
    CP_COMMIT;
    #pragma unroll
    for (int nt = 0; nt < 4; nt++)          // vnorm -> A cols 256-511
        #pragma unroll
        for (int jr = 0; jr < 2; jr++) {
            int r = mb + g8 + jr * 8;
            int c0 = nb + nt * 8 + tid2;
            int idx = nt * 4 + jr * 2;
            float s0 = sqrtf(vn2[idx] + 1e-8f);
            float s1 = sqrtf(vn2[idx + 1] + 1e-8f);
            u32 hi, lo;
            split2(s0, s1, hi, lo);
            STS32(a_addr(Ab, r, 256 + c0), hi);
            STS32(a_addr(Ab, r, 384 + c0), lo);
        }
    CP_WAIT0;
    BARG;
    gemm3(hacc, Ab, Bb, mb, nb, lane, 256, 384);

    BARG;
    cp_img(Bb, g_img[4], tg);               // W2 tile a
    CP_COMMIT;
    #pragma unroll
    for (int nt = 0; nt < 4; nt++)          // silu(h) -> A cols 0-255
        #pragma unroll
        for (int jr = 0; jr < 2; jr++) {
            int r = mb + g8 + jr * 8;
            int c0 = nb + nt * 8 + tid2;
            int idx = nt * 4 + jr * 2;
            float z0 = hacc[idx]     + __ldg(b1 + c0);
            float z1 = hacc[idx + 1] + __ldg(b1 + c0 + 1);
            float s0 = __fdividef(z0, 1.f + __expf(-z0));
            float s1 = __fdividef(z1, 1.f + __expf(-z1));
            u32 hi, lo;
            split2(s0, s1, hi, lo);
            STS32(a_addr(Ab, r, c0), hi);
            STS32(a_addr(Ab, r, 128 + c0), lo);
        }
    CP_WAIT0;
    BARG;

    // ======== MLP2 ========
    float aacc[16];
    #pragma unroll
    for (int x = 0; x < 16; x++) aacc[x] = 0.f;
    gemm3(aacc, Ab, Bb, mb, nb, lane, 0, 128);
    BARG;
    cp_img(Bb, g_img[5], tg);               // W2 tile b (async, overlaps epilogue)
    CP_COMMIT;

    // delta_v = (a + b2a) * u_i
    #pragma unroll
    for (int nt = 0; nt < 4; nt++)
        #pragma unroll
        for (int jr = 0; jr < 2; jr++) {
            int r = mb + g8 + jr * 8;
            #pragma unroll
            for (int jc = 0; jc < 2; jc++) {
                int c = nb + nt * 8 + tid2 + jc;
                int idx = nt * 4 + jr * 2 + jc;
                float a = aacc[idx] + __ldg(b2 + c);
                float* dst = out + (g0 + r) * 384 + c * 3;
                dst[0] = a * uacc[0][idx];
                dst[1] = a * uacc[1][idx];
                dst[2] = a * uacc[2][idx];
            }
        }
    CP_WAIT0;
    BARG;

    float bacc[16];
    #pragma unroll
    for (int x = 0; x < 16; x++) bacc[x] = 0.f;
    gemm3(bacc, Ab, Bb, mb, nb, lane, 0, 128);
    BARG;
    cp_img(Bb, g_img[6], tg);               // W2 tile c
    CP_COMMIT;
    CP_WAIT0;
    BARG;

    float cacc[16];
    #pragma unroll
    for (int x = 0; x < 16; x++) cacc[x] = 0.f;
    gemm3(cacc, Ab, Bb, mb, nb, lane, 0, 128);

    float* ds = out + (long long)Ntok * 384;
    #pragma unroll
    for (int nt = 0; nt < 4; nt++)
        #pragma unroll
        for (int jr = 0; jr < 2; jr++) {
            int r = mb + g8 + jr * 8;
            int c0 = nb + nt * 8 + tid2;
            int idx = nt * 4 + jr * 2;
            float d0 = (bacc[idx]     + __ldg(b2 + 128 + c0))
                     + (cacc[idx]     + __ldg(b2 + 256 + c0)) * dot[idx];
            float d1 = (bacc[idx + 1] + __ldg(b2 + 129 + c0))
                     + (cacc[idx + 1] + __ldg(b2 + 257 + c0)) * dot[idx + 1];
            *(float2*)(ds + (g0 + r) * 128 + c0) = make_float2(d0, d1);
        }
}

extern "C" void kernel_launch(void* const* d_in, const int* in_sizes, int n_in,
                              void* d_out, int out_size) {
    const float* ve = (const float*)d_in[0];
    const float* se = (const float*)d_in[1];
    const float* Uw = (const float*)d_in[2];
    const float* Vw = (const float*)d_in[3];
    const float* W1 = (const float*)d_in[4];
    const float* b1 = (const float*)d_in[5];
    const float* W2 = (const float*)d_in[6];
    const float* b2 = (const float*)d_in[7];
    float* out = (float*)d_out;

    const int N = in_sizes[0] / 384;        // 262144
    const int smem_bytes = 196608;          // 192 KB

    cudaFuncSetAttribute(update_kernel, cudaFuncAttributeMaxDynamicSharedMemorySize, smem_bytes);

    prep_kernel<<<448, 512>>>(Uw, Vw, W1, W2);
    update_kernel<<<N / 64, 512, smem_bytes>>>(ve, se, b1, b2, out, N);
}

// round 6
// speedup vs baseline: 5.1912x; 1.2899x over previous
#include <cuda_runtime.h>
#include <cuda_bf16.h>

typedef unsigned int u32;
typedef unsigned short u16;

// Problem: N=262144 tokens, C=128.
//   d_in: ve [N,128,3] f32, se [N,128], U_w[128,128], V_w[128,128],
//         W1[128,256], b1[128], W2[384,128], b2[384]
//   out: delta_v [N,128,3] then delta_s [N,128]
//
// mma.sync m16n8k16 bf16, hi/lo 3-term split with FUSED fragment reuse:
// per k-chunk load ah,al,Bh,Bl once -> 6 MMAs (vs 9 loads before).
// Phase A computes u and v together from one A fill (U and V images resident).
// Weight images (pre-swizzled, [256 rows hi|lo][128 cols]) in device globals:
// 0=U^T 1=V^T 2=W1^T k0 3=W1^T k1 4..6=W2^T a,b,c

__device__ __align__(16) u16 g_img[7][32768];

__host__ __device__ __forceinline__ int img_byte(int r, int c) {
    return r * 256 + ((((c >> 3) ^ (r & 7)) << 4) | ((c & 7) << 1));
}

__global__ void prep_kernel(const float* __restrict__ U, const float* __restrict__ V,
                            const float* __restrict__ W1, const float* __restrict__ W2) {
    int t = blockIdx.x * blockDim.x + threadIdx.x;
    if (t >= 7 * 32768) return;
    int img = t >> 15, e = t & 32767;
    int r = e >> 7, n = e & 127, k = r & 127;
    float val;
    switch (img) {
        case 0:  val = U[n * 128 + k]; break;
        case 1:  val = V[n * 128 + k]; break;
        case 2:  val = W1[n * 256 + k]; break;
        case 3:  val = W1[n * 256 + 128 + k]; break;
        case 4:  val = W2[n * 128 + k]; break;
        case 5:  val = W2[(128 + n) * 128 + k]; break;
        default: val = W2[(256 + n) * 128 + k]; break;
    }
    __nv_bfloat16 h = __float2bfloat16(val);
    u16 w = (r < 128) ? __bfloat16_as_ushort(h)
                      : __bfloat16_as_ushort(__float2bfloat16(val - __bfloat162float(h)));
    g_img[img][img_byte(r, n) >> 1] = w;
}

// ---------------- device helpers ----------------
__device__ __forceinline__ u32 a_addr(u32 Ab, int r, int c) {   // A: 64 rows x 1KB
    return Ab + r * 1024 + ((((c >> 3) ^ (r & 7)) << 4) | ((c & 7) << 1));
}
__device__ __forceinline__ void split2(float x0, float x1, u32& hi, u32& lo) {
    __nv_bfloat16 h0 = __float2bfloat16(x0), h1 = __float2bfloat16(x1);
    __nv_bfloat16 l0 = __float2bfloat16(x0 - __bfloat162float(h0));
    __nv_bfloat16 l1 = __float2bfloat16(x1 - __bfloat162float(h1));
    hi = ((u32)__bfloat16_as_ushort(h1) << 16) | __bfloat16_as_ushort(h0);
    lo = ((u32)__bfloat16_as_ushort(l1) << 16) | __bfloat16_as_ushort(l0);
}
#define STS32(a, v)      asm volatile("st.shared.u32 [%0], %1;" :: "r"(a), "r"(v))
#define LDS2F(x, y, a)   asm volatile("ld.shared.v2.f32 {%0,%1}, [%2];" : "=f"(x), "=f"(y) : "r"(a))
#define STS2F(a, x, y)   asm volatile("st.shared.v2.f32 [%0], {%1,%2};" :: "r"(a), "f"(x), "f"(y))
#define CP_COMMIT        asm volatile("cp.async.commit_group;")
#define CP_WAIT0         asm volatile("cp.async.wait_group 0;" ::: "memory")
#define CP_WAIT1         asm volatile("cp.async.wait_group 1;" ::: "memory")

#define LDMX4(r0,r1,r2,r3,addr) \
    asm volatile("ldmatrix.sync.aligned.m8n8.x4.shared.b16 {%0,%1,%2,%3}, [%4];" \
                 : "=r"(r0), "=r"(r1), "=r"(r2), "=r"(r3) : "r"(addr))
#define LDMX4T(r0,r1,r2,r3,addr) \
    asm volatile("ldmatrix.sync.aligned.m8n8.x4.trans.shared.b16 {%0,%1,%2,%3}, [%4];" \
                 : "=r"(r0), "=r"(r1), "=r"(r2), "=r"(r3) : "r"(addr))
#define MMA4(D, A0,A1,A2,A3, B0r,B1r) \
    asm volatile("mma.sync.aligned.m16n8k16.row.col.f32.bf16.bf16.f32 " \
                 "{%0,%1,%2,%3},{%4,%5,%6,%7},{%8,%9},{%0,%1,%2,%3};" \
                 : "+f"((D)[0]), "+f"((D)[1]), "+f"((D)[2]), "+f"((D)[3]) \
                 : "r"(A0),"r"(A1),"r"(A2),"r"(A3), "r"(B0r),"r"(B1r))

__device__ __forceinline__ void cp_img(u32 sdst, const u16* src, int t) {
    #pragma unroll
    for (int q = 0; q < 8; q++) {
        int idx = t + q * 512;
        asm volatile("cp.async.cg.shared.global [%0], [%1], 16;"
                     :: "r"(sdst + idx * 16), "l"((const char*)src + idx * 16));
    }
}

// fused 3-term GEMM over one B image: acc[m16,n32] += split(A) * split(B)
__device__ __forceinline__ void gemm_f(float* acc, u32 Ab, u32 Bb,
                                       int mb, int nb, int lane, int ah, int al) {
    const int ra = mb + (lane & 15);
    const int half8 = (lane >> 4) << 3;
    const int rbl = lane & 15;
    #pragma unroll
    for (int kc = 0; kc < 8; kc++) {
        int ch = ah + kc * 16 + half8, cl = al + kc * 16 + half8;
        u32 h0,h1,h2,h3, l0,l1,l2,l3;
        LDMX4(h0,h1,h2,h3, Ab + ra * 1024 + ((((ch >> 3) ^ (ra & 7)) << 4)));
        LDMX4(l0,l1,l2,l3, Ab + ra * 1024 + ((((cl >> 3) ^ (ra & 7)) << 4)));
        int rbh = kc * 16 + rbl, rblo = 128 + rbh;
        #pragma unroll
        for (int np = 0; np < 2; np++) {
            int cb = nb + np * 16 + half8;
            u32 p0,p1,p2,p3, q0,q1,q2,q3;
            LDMX4T(p0,p1,p2,p3, Bb + rbh  * 256 + ((((cb >> 3) ^ (rbh  & 7)) << 4)));
            LDMX4T(q0,q1,q2,q3, Bb + rblo * 256 + ((((cb >> 3) ^ (rblo & 7)) << 4)));
            float* d0 = acc + np * 8;
            float* d1 = d0 + 4;
            MMA4(d0, h0,h1,h2,h3, p0,p1);  MMA4(d1, h0,h1,h2,h3, p2,p3);
            MMA4(d0, l0,l1,l2,l3, p0,p1);  MMA4(d1, l0,l1,l2,l3, p2,p3);
            MMA4(d0, h0,h1,h2,h3, q0,q1);  MMA4(d1, h0,h1,h2,h3, q2,q3);
        }
    }
}

// phase-A: u and v together, A fragments shared across both weight images
__device__ __forceinline__ void gemm_uv(float* ua, float* va, u32 Ab, u32 BU, u32 BV,
                                        int mb, int nb, int lane) {
    const int ra = mb + (lane & 15);
    const int half8 = (lane >> 4) << 3;
    const int rbl = lane & 15;
    #pragma unroll
    for (int kc = 0; kc < 8; kc++) {
        int ch = kc * 16 + half8, cl = 128 + ch;
        u32 h0,h1,h2,h3, l0,l1,l2,l3;
        LDMX4(h0,h1,h2,h3, Ab + ra * 1024 + ((((ch >> 3) ^ (ra & 7)) << 4)));
        LDMX4(l0,l1,l2,l3, Ab + ra * 1024 + ((((cl >> 3) ^ (ra & 7)) << 4)));
        int rbh = kc * 16 + rbl, rblo = 128 + rbh;
        #pragma unroll
        for (int np = 0; np < 2; np++) {
            int cb = nb + np * 16 + half8;
            u32 boffh = rbh * 256 + ((((cb >> 3) ^ (rbh & 7)) << 4));
            u32 boffl = rblo * 256 + ((((cb >> 3) ^ (rblo & 7)) << 4));
            #pragma unroll
            for (int im = 0; im < 2; im++) {
                u32 Bb = im ? BV : BU;
                float* acc = (im ? va : ua) + np * 8;
                u32 p0,p1,p2,p3, q0,q1,q2,q3;
                LDMX4T(p0,p1,p2,p3, Bb + boffh);
                LDMX4T(q0,q1,q2,q3, Bb + boffl);
                float* d1 = acc + 4;
                MMA4(acc, h0,h1,h2,h3, p0,p1);  MMA4(d1, h0,h1,h2,h3, p2,p3);
                MMA4(acc, l0,l1,l2,l3, p0,p1);  MMA4(d1, l0,l1,l2,l3, p2,p3);
                MMA4(acc, h0,h1,h2,h3, q0,q1);  MMA4(d1, h0,h1,h2,h3, q2,q3);
            }
        }
    }
}

// fill x_i (component i of ve) -> A cols 0-127 hi, 128-255 lo (64 rows)
__device__ __forceinline__ void fill_x(u32 Ab, const float* __restrict__ ve,
                                       long long n0, int i, int t) {
    #pragma unroll
    for (int q = 0; q < 8; q++) {
        int p = t + q * 512;
        int r = p >> 6, c0 = (p & 63) << 1;
        const float* g = ve + (n0 + r) * 384 + c0 * 3 + i;
        float x0 = __ldg(g), x1 = __ldg(g + 3);
        u32 hi, lo;
        split2(x0, x1, hi, lo);
        STS32(a_addr(Ab, r, c0), hi);
        STS32(a_addr(Ab, r, 128 + c0), lo);
    }
}

// ---------------- main kernel ----------------
// smem: A @0 (64KB; during phase A bytes 512-1023/row = vn2 scratch),
//       B0 @64KB, B1 @128KB   -> 192KB
__global__ __launch_bounds__(512, 1)
void update_kernel(const float* __restrict__ ve, const float* __restrict__ se,
                   const float* __restrict__ b1, const float* __restrict__ b2,
                   float* __restrict__ out, int Ntok) {
    extern __shared__ __align__(128) unsigned char smraw[];
    const u32 Ab = (u32)__cvta_generic_to_shared(smraw);
    const u32 B0 = Ab + 65536, B1 = Ab + 131072;

    const int t = threadIdx.x, lane = t & 31, warp = t >> 5;
    const int mb = (warp >> 2) << 4;      // 0,16,32,48
    const int nb = (warp & 3) << 5;       // 0,32,64,96
    const int g8 = lane >> 2, tid2 = (lane & 3) << 1;
    const long long n0 = (long long)blockIdx.x * 64;

    cp_img(B0, g_img[0], t);              // U
    cp_img(B1, g_img[1], t);              // V
    CP_COMMIT;
    fill_x(Ab, ve, n0, 0, t);
    CP_WAIT0;
    __syncthreads();

    float uacc[3][16], dot[16];
    #pragma unroll
    for (int x = 0; x < 16; x++) dot[x] = 0.f;

    // ======== phase A: u_i & v_i together per component ========
    #pragma unroll
    for (int i = 0; i < 3; i++) {
        float vacc[16];
        #pragma unroll
        for (int x = 0; x < 16; x++) { uacc[i][x] = 0.f; vacc[x] = 0.f; }
        gemm_uv(uacc[i], vacc, Ab, B0, B1, mb, nb, lane);
        #pragma unroll
        for (int x = 0; x < 16; x++) dot[x] = fmaf(uacc[i][x], vacc[x], dot[x]);
        // vn2 scratch in A bytes 512-1023 (exclusive per-thread cells)
        #pragma unroll
        for (int nt = 0; nt < 4; nt++)
            #pragma unroll
            for (int jr = 0; jr < 2; jr++) {
                int r = mb + g8 + jr * 8;
                int c0 = nb + nt * 8 + tid2;
                u32 ad = Ab + r * 1024 + 512 + c0 * 4;
                int idx = nt * 4 + jr * 2;
                float v0 = vacc[idx], v1 = vacc[idx + 1];
                if (i == 0) {
                    STS2F(ad, v0 * v0, v1 * v1);
                } else {
                    float p0, p1;
                    LDS2F(p0, p1, ad);
                    STS2F(ad, fmaf(v0, v0, p0), fmaf(v1, v1, p1));
                }
            }
        if (i < 2) {
            __syncthreads();
            fill_x(Ab, ve, n0, i + 1, t);
            __syncthreads();
        }
    }
    __syncthreads();                      // all phase-A A reads done

    // ======== mvec = [se | vnorm] ========
    float vnr[16];
    #pragma unroll
    for (int nt = 0; nt < 4; nt++)
        #pragma unroll
        for (int jr = 0; jr < 2; jr++) {
            int r = mb + g8 + jr * 8;
            int c0 = nb + nt * 8 + tid2;
            LDS2F(vnr[nt * 4 + jr * 2], vnr[nt * 4 + jr * 2 + 1],
                  Ab + r * 1024 + 512 + c0 * 4);
        }
    cp_img(B0, g_img[2], t);              // W1 k-half0
    cp_img(B1, g_img[3], t);              // W1 k-half1
    CP_COMMIT;
    #pragma unroll
    for (int q = 0; q < 8; q++) {         // se -> A cols 0-255
        int p = t + q * 512;
        int r = p >> 6, c0 = (p & 63) << 1;
        float2 v = *(const float2*)(se + (n0 + r) * 128 + c0);
        u32 hi, lo;
        split2(v.x, v.y, hi, lo);
        STS32(a_addr(Ab, r, c0), hi);
        STS32(a_addr(Ab, r, 128 + c0), lo);
    }
    __syncthreads();                      // all vn2 scratch reads done
    #pragma unroll
    for (int nt = 0; nt < 4; nt++)        // vnorm -> A cols 256-511
        #pragma unroll
        for (int jr = 0; jr < 2; jr++) {
            int r = mb + g8 + jr * 8;
            int c0 = nb + nt * 8 + tid2;
            int idx = nt * 4 + jr * 2;
            float s0 = sqrtf(vnr[idx] + 1e-8f);
            float s1 = sqrtf(vnr[idx + 1] + 1e-8f);
            u32 hi, lo;
            split2(s0, s1, hi, lo);
            STS32(a_addr(Ab, r, 256 + c0), hi);
            STS32(a_addr(Ab, r, 384 + c0), lo);
        }
    CP_WAIT0;
    __syncthreads();

    // ======== MLP1 ========
    float hacc[16];
    #pragma unroll
    for (int x = 0; x < 16; x++) hacc[x] = 0.f;
    gemm_f(hacc, Ab, B0, mb, nb, lane, 0, 128);
    __syncthreads();                      // B0 free
    cp_img(B0, g_img[4], t);              // W2 tile a
    CP_COMMIT;
    gemm_f(hacc, Ab, B1, mb, nb, lane, 256, 384);
    CP_WAIT0;                             // W2a arrived
    __syncthreads();                      // B1 + A reads done
    #pragma unroll
    for (int nt = 0; nt < 4; nt++)        // silu(h) -> A cols 0-255
        #pragma unroll
        for (int jr = 0; jr < 2; jr++) {
            int r = mb + g8 + jr * 8;
            int c0 = nb + nt * 8 + tid2;
            int idx = nt * 4 + jr * 2;
            float z0 = hacc[idx]     + __ldg(b1 + c0);
            float z1 = hacc[idx + 1] + __ldg(b1 + c0 + 1);
            float s0 = __fdividef(z0, 1.f + __expf(-z0));
            float s1 = __fdividef(z1, 1.f + __expf(-z1));
            u32 hi, lo;
            split2(s0, s1, hi, lo);
            STS32(a_addr(Ab, r, c0), hi);
            STS32(a_addr(Ab, r, 128 + c0), lo);
        }
    cp_img(B1, g_img[5], t);              // W2 tile b
    CP_COMMIT;
    __syncthreads();                      // silu visible

    // ======== MLP2 ========
    float aacc[16];
    #pragma unroll
    for (int x = 0; x < 16; x++) aacc[x] = 0.f;
    gemm_f(aacc, Ab, B0, mb, nb, lane, 0, 128);
    __syncthreads();                      // B0 reads done
    cp_img(B0, g_img[6], t);              // W2 tile c (behind epilogue)
    CP_COMMIT;

    // delta_v = (a + b2a) * u_i
    #pragma unroll
    for (int nt = 0; nt < 4; nt++)
        #pragma unroll
        for (int jr = 0; jr < 2; jr++) {
            int r = mb + g8 + jr * 8;
            #pragma unroll
            for (int jc = 0; jc < 2; jc++) {
                int c = nb + nt * 8 + tid2 + jc;
                int idx = nt * 4 + jr * 2 + jc;
                float a = aacc[idx] + __ldg(b2 + c);
                float* dst = out + (n0 + r) * 384 + c * 3;
                dst[0] = a * uacc[0][idx];
                dst[1] = a * uacc[1][idx];
                dst[2] = a * uacc[2][idx];
            }
        }
    CP_WAIT1;                             // W2b done (W2c may be in flight)
    __syncthreads();

    float bacc[16];
    #pragma unroll
    for (int x = 0; x < 16; x++) bacc[x] = 0.f;
    gemm_f(bacc, Ab, B1, mb, nb, lane, 0, 128);
    CP_WAIT0;                             // W2c done
    __syncthreads();

    float cacc[16];
    #pragma unroll
    for (int x = 0; x < 16; x++) cacc[x] = 0.f;
    gemm_f(cacc, Ab, B0, mb, nb, lane, 0, 128);

    float* ds = out + (long long)Ntok * 384;
    #pragma unroll
    for (int nt = 0; nt < 4; nt++)
        #pragma unroll
        for (int jr = 0; jr < 2; jr++) {
            int r = mb + g8 + jr * 8;
            int c0 = nb + nt * 8 + tid2;
            int idx = nt * 4 + jr * 2;
            float d0 = (bacc[idx]     + __ldg(b2 + 128 + c0))
                     + (cacc[idx]     + __ldg(b2 + 256 + c0)) * dot[idx];
            float d1 = (bacc[idx + 1] + __ldg(b2 + 129 + c0))
                     + (cacc[idx + 1] + __ldg(b2 + 257 + c0)) * dot[idx + 1];
            *(float2*)(ds + (n0 + r) * 128 + c0) = make_float2(d0, d1);
        }
}

extern "C" void kernel_launch(void* const* d_in, const int* in_sizes, int n_in,
                              void* d_out, int out_size) {
    const float* ve = (const float*)d_in[0];
    const float* se = (const float*)d_in[1];
    const float* Uw = (const float*)d_in[2];
    const float* Vw = (const float*)d_in[3];
    const float* W1 = (const float*)d_in[4];
    const float* b1 = (const float*)d_in[5];
    const float* W2 = (const float*)d_in[6];
    const float* b2 = (const float*)d_in[7];
    float* out = (float*)d_out;

    const int N = in_sizes[0] / 384;        // 262144
    const int smem_bytes = 196608;          // 192 KB

    cudaFuncSetAttribute(update_kernel, cudaFuncAttributeMaxDynamicSharedMemorySize, smem_bytes);

    prep_kernel<<<448, 512>>>(Uw, Vw, W1, W2);
    update_kernel<<<N / 64, 512, smem_bytes>>>(ve, se, b1, b2, out, N);
}